// round 8
// baseline (speedup 1.0000x reference)
#include <cuda_runtime.h>
#include <math.h>

// Problem constants
#define NB     64
#define TT     2048
#define FRAME  512
#define ENCC   256
#define HIDD   128
#define GATES  512
#define MROWS  (NB * TT)          // 131072

// ---------------- scratch (device globals; no allocation allowed) ----------------
__device__ float  g_encf[MROWS * ENCC];   // 134 MB: encoder output [m][e] (pre-norm), later est in-place
__device__ float  g_xg  [MROWS * GATES];  // 268 MB: precomputed input gates (reused by both LSTMs)
__device__ float  g_x1  [MROWS * HIDD];   // LSTM1 hidden sequence
__device__ float  g_x2  [MROWS * HIDD];   // LSTM2 hidden sequence
__device__ double g_part[2048];           // reduction partials (1024 sums + 1024 sumsqs)
__device__ float  g_mean, g_rstd;

__device__ __forceinline__ float sigmoidf_(float x) { return 1.f / (1.f + expf(-x)); }

// ---------------- generic tiled fp32 GEMM: C = A @ B^T (+mode-specific fusion) ----------------
// B is always row-major weights [NC][K]. BM=BN=128, BK=16, 256 threads, 8x8 microtile.
#define BM 128
#define BN 128
#define BK 16

enum GemmMode { MODE_ENC = 0, MODE_XG1 = 1, MODE_XG2 = 2, MODE_MASK = 3, MODE_DEC = 4 };

template <int MODE, int K, int NC>
__global__ void __launch_bounds__(256) gemm_kernel(
    const float* __restrict__ A, const float* __restrict__ B, float* __restrict__ C,
    const float* __restrict__ bias1, const float* __restrict__ bias2,
    const float* __restrict__ gamma, const float* __restrict__ beta)
{
    __shared__ float As[BK][BM];
    __shared__ float Bs[BK][BN];

    const int tid      = threadIdx.x;
    const int row_base = (tid & 15) * 8;
    const int col_base = (tid >> 4) * 8;
    const int m0       = blockIdx.y * BM;
    const int j0       = blockIdx.x * BN;

    float mn = 0.f, rs = 0.f;
    if (MODE == MODE_XG1) { mn = g_mean; rs = g_rstd; }

    float acc[8][8];
#pragma unroll
    for (int i = 0; i < 8; ++i)
#pragma unroll
        for (int j = 0; j < 8; ++j) acc[i][j] = 0.f;

    for (int k0 = 0; k0 < K; k0 += BK) {
        // ---- load A tile into As[k][m] ----
        if (MODE == MODE_ENC) {
            // A = y1 [NB][FRAME][TT]; row m=(n,t): a(m,k)=y1[n][k][t]; tiles never cross n (128|2048)
            const int n  = m0 >> 11;
            const int t0 = m0 & (TT - 1);
#pragma unroll
            for (int it = 0; it < 2; ++it) {
                int q  = tid + it * 256;
                int kk = q >> 5;
                int tv = (q & 31) * 4;
                const float4 v = *(const float4*)(A + ((size_t)(n * FRAME + k0 + kk)) * TT + t0 + tv);
                *(float4*)(&As[kk][tv]) = v;
            }
        } else {
            // A row-major [m][K]
#pragma unroll
            for (int it = 0; it < 2; ++it) {
                int q   = tid + it * 256;
                int row = q >> 2;
                int kv  = (q & 3) * 4;
                float4 v = *(const float4*)(A + (size_t)(m0 + row) * K + k0 + kv);
                if (MODE == MODE_XG1) {  // fuse global layernorm into A-read
                    v.x = (v.x - mn) * rs * gamma[k0 + kv + 0] + beta[k0 + kv + 0];
                    v.y = (v.y - mn) * rs * gamma[k0 + kv + 1] + beta[k0 + kv + 1];
                    v.z = (v.z - mn) * rs * gamma[k0 + kv + 2] + beta[k0 + kv + 2];
                    v.w = (v.w - mn) * rs * gamma[k0 + kv + 3] + beta[k0 + kv + 3];
                }
                As[kv + 0][row] = v.x; As[kv + 1][row] = v.y;
                As[kv + 2][row] = v.z; As[kv + 3][row] = v.w;
            }
        }
        // ---- load B tile (weights [NC][K]) into Bs[k][j] ----
#pragma unroll
        for (int it = 0; it < 2; ++it) {
            int q  = tid + it * 256;
            int jj = q >> 2;
            int kv = (q & 3) * 4;
            const float4 v = *(const float4*)(B + (size_t)(j0 + jj) * K + k0 + kv);
            Bs[kv + 0][jj] = v.x; Bs[kv + 1][jj] = v.y;
            Bs[kv + 2][jj] = v.z; Bs[kv + 3][jj] = v.w;
        }
        __syncthreads();
#pragma unroll
        for (int kk = 0; kk < BK; ++kk) {
            float a[8], b[8];
            *(float4*)(a)     = *(const float4*)(&As[kk][row_base]);
            *(float4*)(a + 4) = *(const float4*)(&As[kk][row_base + 4]);
            *(float4*)(b)     = *(const float4*)(&Bs[kk][col_base]);
            *(float4*)(b + 4) = *(const float4*)(&Bs[kk][col_base + 4]);
#pragma unroll
            for (int i = 0; i < 8; ++i)
#pragma unroll
                for (int j = 0; j < 8; ++j) acc[i][j] += a[i] * b[j];
        }
        __syncthreads();
    }

    // ---- epilogue ----
    if (MODE == MODE_DEC) {
        // C = d_out [NB][FRAME][TT]; vectorize along t (thread's contiguous rows)
        const int n     = m0 >> 11;
        const int tbase = (m0 & (TT - 1)) + row_base;
#pragma unroll
        for (int j = 0; j < 8; ++j) {
            const int col = j0 + col_base + j;
            float* p = C + ((size_t)n * FRAME + col) * TT + tbase;
            *(float4*)(p)     = make_float4(acc[0][j], acc[1][j], acc[2][j], acc[3][j]);
            *(float4*)(p + 4) = make_float4(acc[4][j], acc[5][j], acc[6][j], acc[7][j]);
        }
    } else {
        float bj[8];
#pragma unroll
        for (int j = 0; j < 8; ++j) {
            const int col = j0 + col_base + j;
            if (MODE == MODE_XG1 || MODE == MODE_XG2) bj[j] = bias1[col] + bias2[col];
            else if (MODE == MODE_MASK)               bj[j] = bias1[col];
            else                                      bj[j] = 0.f;
        }
#pragma unroll
        for (int i = 0; i < 8; ++i) {
            float* p = C + (size_t)(m0 + row_base + i) * NC + j0 + col_base;
            if (MODE == MODE_MASK) {
                // est = sigmoid(x2@Wd^T + bd) * encf  (in place into encf)
                float4 e0 = *(const float4*)(p);
                float4 e1 = *(const float4*)(p + 4);
                float4 v0, v1;
                v0.x = sigmoidf_(acc[i][0] + bj[0]) * e0.x;
                v0.y = sigmoidf_(acc[i][1] + bj[1]) * e0.y;
                v0.z = sigmoidf_(acc[i][2] + bj[2]) * e0.z;
                v0.w = sigmoidf_(acc[i][3] + bj[3]) * e0.w;
                v1.x = sigmoidf_(acc[i][4] + bj[4]) * e1.x;
                v1.y = sigmoidf_(acc[i][5] + bj[5]) * e1.y;
                v1.z = sigmoidf_(acc[i][6] + bj[6]) * e1.z;
                v1.w = sigmoidf_(acc[i][7] + bj[7]) * e1.w;
                *(float4*)(p)     = v0;
                *(float4*)(p + 4) = v1;
            } else {
                *(float4*)(p)     = make_float4(acc[i][0] + bj[0], acc[i][1] + bj[1],
                                                acc[i][2] + bj[2], acc[i][3] + bj[3]);
                *(float4*)(p + 4) = make_float4(acc[i][4] + bj[4], acc[i][5] + bj[5],
                                                acc[i][6] + bj[6], acc[i][7] + bj[7]);
            }
        }
    }
}

// ---------------- deterministic global mean/var reduction ----------------
__global__ void reduce_kernel(const float* __restrict__ x, int n)
{
    __shared__ double sh[256];
    __shared__ double sh2[256];
    double s = 0.0, s2 = 0.0;
    for (int i = blockIdx.x * blockDim.x + threadIdx.x; i < n; i += gridDim.x * blockDim.x) {
        double v = (double)x[i];
        s += v; s2 += v * v;
    }
    sh[threadIdx.x] = s; sh2[threadIdx.x] = s2;
    __syncthreads();
    for (int off = 128; off > 0; off >>= 1) {
        if (threadIdx.x < off) {
            sh[threadIdx.x]  += sh[threadIdx.x + off];
            sh2[threadIdx.x] += sh2[threadIdx.x + off];
        }
        __syncthreads();
    }
    if (threadIdx.x == 0) {
        g_part[blockIdx.x]        = sh[0];
        g_part[1024 + blockIdx.x] = sh2[0];
    }
}

__global__ void finalize_kernel()
{
    __shared__ double sh[256];
    __shared__ double sh2[256];
    double s = 0.0, s2 = 0.0;
    for (int i = threadIdx.x; i < 1024; i += 256) { s += g_part[i]; s2 += g_part[1024 + i]; }
    sh[threadIdx.x] = s; sh2[threadIdx.x] = s2;
    __syncthreads();
    for (int off = 128; off > 0; off >>= 1) {
        if (threadIdx.x < off) {
            sh[threadIdx.x]  += sh[threadIdx.x + off];
            sh2[threadIdx.x] += sh2[threadIdx.x + off];
        }
        __syncthreads();
    }
    if (threadIdx.x == 0) {
        const double cnt  = (double)MROWS * (double)ENCC;
        const double mean = sh[0] / cnt;
        const double var  = sh2[0] / cnt - mean * mean;
        g_mean = (float)mean;
        g_rstd = (float)(1.0 / sqrt(var + 1e-7));
    }
}

// ---------------- persistent per-sample LSTM ----------------
// 64 blocks (1 per sample), 512 threads (1 per gate). Whh row split: cols [0,80) in smem
// (pitch 84 floats -> conflict-free float4 reads), cols [80,128) in registers. fp32-exact.
#define LSTM_SK    80
#define LSTM_RK    48
#define LSTM_PITCH 84
#define LSTM_SMEM  ((512 * LSTM_PITCH + 128 + 512) * 4)   // 174592 bytes

__global__ void __launch_bounds__(512, 1) lstm_kernel(
    const float* __restrict__ xg, const float* __restrict__ Whh,
    const float* __restrict__ states_in, float* __restrict__ states_out,
    float* __restrict__ xout, int slot_h, int slot_c)
{
    extern __shared__ float sm[];
    float* whh_sm = sm;                        // [512][84]
    float* h_sh   = sm + 512 * LSTM_PITCH;     // [128]
    float* gates  = h_sh + 128;                // [512]

    const int tid = threadIdx.x;
    const int n   = blockIdx.x;

    // load smem half of this gate's Whh row
#pragma unroll
    for (int k = 0; k < LSTM_SK; k += 4) {
        float4 v = *(const float4*)(Whh + (size_t)tid * HIDD + k);
        *(float4*)(&whh_sm[tid * LSTM_PITCH + k]) = v;
    }
    // register half
    float w[LSTM_RK];
#pragma unroll
    for (int r = 0; r < LSTM_RK; r += 4) {
        float4 v = *(const float4*)(Whh + (size_t)tid * HIDD + LSTM_SK + r);
        w[r] = v.x; w[r + 1] = v.y; w[r + 2] = v.z; w[r + 3] = v.w;
    }

    float c = 0.f;
    if (tid < HIDD) {
        h_sh[tid] = states_in[(size_t)slot_h * (NB * HIDD) + n * HIDD + tid];
        c         = states_in[(size_t)slot_c * (NB * HIDD) + n * HIDD + tid];
    }
    __syncthreads();

    const float* xg_n = xg   + (size_t)n * TT * GATES;
    float*       xo_n = xout + (size_t)n * TT * HIDD;
    const float* wr   = &whh_sm[tid * LSTM_PITCH];

    float xval = xg_n[tid];   // prefetched input gate for t=0 (includes bih+bhh)
    for (int t = 0; t < TT; ++t) {
        // prefetch next step's input gate (hidden behind the GEMV)
        float xnext = (t + 1 < TT) ? xg_n[(size_t)(t + 1) * GATES + tid] : 0.f;

        float a0 = 0.f, a1 = 0.f, a2 = 0.f, a3 = 0.f;
#pragma unroll
        for (int k = 0; k < LSTM_SK; k += 4) {
            float4 h4 = *(const float4*)(&h_sh[k]);
            float4 w4 = *(const float4*)(wr + k);
            a0 += w4.x * h4.x; a1 += w4.y * h4.y; a2 += w4.z * h4.z; a3 += w4.w * h4.w;
        }
#pragma unroll
        for (int r = 0; r < LSTM_RK; r += 4) {
            float4 h4 = *(const float4*)(&h_sh[LSTM_SK + r]);
            a0 += w[r] * h4.x; a1 += w[r + 1] * h4.y; a2 += w[r + 2] * h4.z; a3 += w[r + 3] * h4.w;
        }
        gates[tid] = xval + ((a0 + a1) + (a2 + a3));
        __syncthreads();

        if (tid < HIDD) {  // units: i=tid, f=128+tid, g=256+tid, o=384+tid (PyTorch order)
            float iv = sigmoidf_(gates[tid]);
            float fv = sigmoidf_(gates[HIDD + tid]);
            float gv = tanhf(gates[2 * HIDD + tid]);
            float ov = sigmoidf_(gates[3 * HIDD + tid]);
            c = fv * c + iv * gv;
            float h = ov * tanhf(c);
            h_sh[tid] = h;
            xo_n[(size_t)t * HIDD + tid] = h;
        }
        __syncthreads();
        xval = xnext;
    }

    if (tid < HIDD) {
        states_out[(size_t)slot_h * (NB * HIDD) + n * HIDD + tid] = h_sh[tid];
        states_out[(size_t)slot_c * (NB * HIDD) + n * HIDD + tid] = c;
    }
}

// ---------------- launch ----------------
extern "C" void kernel_launch(void* const* d_in, const int* in_sizes, int n_in,
                              void* d_out, int out_size)
{
    const float* y1    = (const float*)d_in[0];
    const float* st_in = (const float*)d_in[1];
    const float* W_enc = (const float*)d_in[2];
    const float* gamma = (const float*)d_in[3];
    const float* beta  = (const float*)d_in[4];
    const float* Wih1  = (const float*)d_in[5];
    const float* Whh1  = (const float*)d_in[6];
    const float* bih1  = (const float*)d_in[7];
    const float* bhh1  = (const float*)d_in[8];
    const float* Wih2  = (const float*)d_in[9];
    const float* Whh2  = (const float*)d_in[10];
    const float* bih2  = (const float*)d_in[11];
    const float* bhh2  = (const float*)d_in[12];
    const float* Wd    = (const float*)d_in[13];
    const float* bd    = (const float*)d_in[14];
    const float* W_dec = (const float*)d_in[15];

    float* out        = (float*)d_out;
    float* states_out = out + ((size_t)out_size - 4 * NB * HIDD);

    float* encf; float* xg; float* x1; float* x2;
    cudaGetSymbolAddress((void**)&encf, g_encf);
    cudaGetSymbolAddress((void**)&xg,   g_xg);
    cudaGetSymbolAddress((void**)&x1,   g_x1);
    cudaGetSymbolAddress((void**)&x2,   g_x2);

    cudaFuncSetAttribute(lstm_kernel, cudaFuncAttributeMaxDynamicSharedMemorySize, LSTM_SMEM);

    const dim3 blk(256);
    const dim3 grid_enc (ENCC  / BN, MROWS / BM);
    const dim3 grid_g512(GATES / BN, MROWS / BM);
    const dim3 grid_mask(ENCC  / BN, MROWS / BM);

    // 1. encoder: encf[m][e] = sum_c W_enc[e,c] * y1[n,c,t]
    gemm_kernel<MODE_ENC, FRAME, ENCC><<<grid_enc, blk>>>(y1, W_enc, encf, 0, 0, 0, 0);
    // 2-3. global scalar mean/var (deterministic two-pass)
    reduce_kernel<<<1024, 256>>>(encf, MROWS * ENCC);
    finalize_kernel<<<1, 256>>>();
    // 4. xg1 = norm(encf) @ Wih1^T + (bih1+bhh1)   (layernorm fused into A-read)
    gemm_kernel<MODE_XG1, ENCC, GATES><<<grid_g512, blk>>>(encf, Wih1, xg, bih1, bhh1, gamma, beta);
    // 5. LSTM1 (slots 0/1) -> x1, states
    lstm_kernel<<<NB, 512, LSTM_SMEM>>>(xg, Whh1, st_in, states_out, x1, 0, 1);
    // 6. xg2 = x1 @ Wih2^T + (bih2+bhh2)
    gemm_kernel<MODE_XG2, HIDD, GATES><<<grid_g512, blk>>>(x1, Wih2, xg, bih2, bhh2, 0, 0);
    // 7. LSTM2 (slots 2/3) -> x2, states
    lstm_kernel<<<NB, 512, LSTM_SMEM>>>(xg, Whh2, st_in, states_out, x2, 2, 3);
    // 8. est = sigmoid(x2 @ Wd^T + bd) * encf   (in place into encf)
    gemm_kernel<MODE_MASK, HIDD, ENCC><<<grid_mask, blk>>>(x2, Wd, encf, bd, 0, 0, 0);
    // 9. decoded[n][f][t] = sum_e W_dec[f,e] * est[m][e]
    gemm_kernel<MODE_DEC, ENCC, FRAME><<<grid_g512, blk>>>(encf, W_dec, out, 0, 0, 0, 0);
}